// round 1
// baseline (speedup 1.0000x reference)
#include <cuda_runtime.h>
#include <math.h>

#define Bdim 128
#define Pdim 256
#define PIXdim 256
#define Ddim 512
#define Cdim 10

#define NSTATE (Bdim*Pdim*Ddim)   // 16,777,216
#define NATTN  (Bdim*Pdim*Pdim)   // 8,388,608
#define NPART  4096

static __device__ float g_state_re[NSTATE];
static __device__ float g_state_im[NSTATE];
static __device__ float g_new_re[NSTATE];
static __device__ float g_new_im[NSTATE];
static __device__ float g_u_re[NSTATE];
static __device__ float g_u_im[NSTATE];
static __device__ float g_attn[NATTN];
static __device__ float g_pool_re[Bdim*Ddim];
static __device__ float g_pool_im[Bdim*Ddim];
static __device__ float g_cd[Ddim], g_sd[Ddim], g_cv[Ddim], g_sv[Ddim];
static __device__ double g_part_d[NPART];
static __device__ double g_part_n[NPART];
static __device__ int g_active;
static __device__ int g_commit;

// ---------------------------------------------------------------- prep
__global__ void k_prep(const float* __restrict__ qr, const float* __restrict__ kr,
                       const float* __restrict__ vr) {
    int d = threadIdx.x;
    if (d < Ddim) {
        float cq, sq, ck, sk, cv, sv;
        sincosf(qr[d], &sq, &cq);
        sincosf(kr[d], &sk, &ck);
        sincosf(vr[d], &sv, &cv);
        // e^{iq} * conj(e^{ik})
        g_cd[d] = cq*ck + sq*sk;
        g_sd[d] = sq*ck - cq*sk;
        g_cv[d] = cv;
        g_sv[d] = sv;
    }
    if (d == 0) { g_active = 1; g_commit = 0; }
}

// ---------------------------------------------------------------- proj: state = tanh(x@Wp^T+bp) * e^{i phase}
__global__ void k_proj(const float* __restrict__ x, const float* __restrict__ Wp,
                       const float* __restrict__ bp) {
    __shared__ float As[16][68];
    __shared__ float Bs[16][68];
    const int tid = threadIdx.x;
    const int m0 = blockIdx.y * 64, n0 = blockIdx.x * 64;
    const int tm = (tid >> 4) * 4, tn = (tid & 15) * 4;
    const int lk = tid & 15, lr = tid >> 4;
    float acc[4][4] = {};
    for (int k0 = 0; k0 < PIXdim; k0 += 16) {
        #pragma unroll
        for (int i = 0; i < 4; i++) {
            As[lk][lr + 16*i] = x [(size_t)(m0 + lr + 16*i) * PIXdim + (k0 + lk)];
            Bs[lk][lr + 16*i] = Wp[(size_t)(n0 + lr + 16*i) * PIXdim + (k0 + lk)];
        }
        __syncthreads();
        #pragma unroll
        for (int kk = 0; kk < 16; kk++) {
            float a[4], b[4];
            #pragma unroll
            for (int i = 0; i < 4; i++) { a[i] = As[kk][tm+i]; b[i] = Bs[kk][tn+i]; }
            #pragma unroll
            for (int i = 0; i < 4; i++)
                #pragma unroll
                for (int j = 0; j < 4; j++)
                    acc[i][j] = fmaf(a[i], b[j], acc[i][j]);
        }
        __syncthreads();
    }
    const float PI = 3.14159265358979323846f;
    #pragma unroll
    for (int j = 0; j < 4; j++) {
        int n = n0 + tn + j;
        float freq = 1.0f / powf(10000.0f, (float)n / (float)Ddim);
        float bpv = bp[n];
        #pragma unroll
        for (int i = 0; i < 4; i++) {
            int m = m0 + tm + i;
            int p = m & (Pdim - 1);
            float t = tanhf(acc[i][j] + bpv);
            float ph = ((float)p * freq) * PI;
            float s, c;
            sincosf(ph, &s, &c);
            size_t idx = (size_t)m * Ddim + n;
            g_state_re[idx] = t * c;
            g_state_im[idx] = t * s;
        }
    }
}

// ---------------------------------------------------------------- QK^H real part * scale
__global__ void k_qk() {
    __shared__ float Ar[16][68], Ai[16][68], Br[16][68], Bi[16][68];
    const int tid = threadIdx.x;
    const int b = blockIdx.z;
    const int p0 = blockIdx.y * 64, q0 = blockIdx.x * 64;
    const int tm = (tid >> 4) * 4, tn = (tid & 15) * 4;
    const int lk = tid & 15, lr = tid >> 4;
    const float* __restrict__ sre = g_state_re + (size_t)b * Pdim * Ddim;
    const float* __restrict__ sim = g_state_im + (size_t)b * Pdim * Ddim;
    float acc[4][4] = {};
    for (int k0 = 0; k0 < Ddim; k0 += 16) {
        int d = k0 + lk;
        float cd = g_cd[d], sd = g_sd[d];
        #pragma unroll
        for (int i = 0; i < 4; i++) {
            int pr = p0 + lr + 16*i;
            float re = sre[(size_t)pr * Ddim + d];
            float im = sim[(size_t)pr * Ddim + d];
            Ar[lk][lr + 16*i] = re * cd - im * sd;
            Ai[lk][lr + 16*i] = re * sd + im * cd;
            int qq = q0 + lr + 16*i;
            Br[lk][lr + 16*i] = sre[(size_t)qq * Ddim + d];
            Bi[lk][lr + 16*i] = sim[(size_t)qq * Ddim + d];
        }
        __syncthreads();
        #pragma unroll
        for (int kk = 0; kk < 16; kk++) {
            float ar[4], ai[4], br[4], bi[4];
            #pragma unroll
            for (int i = 0; i < 4; i++) {
                ar[i] = Ar[kk][tm+i]; ai[i] = Ai[kk][tm+i];
                br[i] = Br[kk][tn+i]; bi[i] = Bi[kk][tn+i];
            }
            #pragma unroll
            for (int i = 0; i < 4; i++)
                #pragma unroll
                for (int j = 0; j < 4; j++) {
                    acc[i][j] = fmaf(ar[i], br[j], acc[i][j]);
                    acc[i][j] = fmaf(ai[i], bi[j], acc[i][j]);
                }
        }
        __syncthreads();
    }
    const float SCALE = 0.3535533905932738f;  // 8/sqrt(512)
    float* out = g_attn + (size_t)b * Pdim * Pdim;
    #pragma unroll
    for (int i = 0; i < 4; i++)
        #pragma unroll
        for (int j = 0; j < 4; j++)
            out[(size_t)(p0 + tm + i) * Pdim + (q0 + tn + j)] = acc[i][j] * SCALE;
}

// ---------------------------------------------------------------- softmax over rows of length 256
__global__ void k_softmax() {
    const int row = blockIdx.x;
    const int tid = threadIdx.x;
    float* a = g_attn + (size_t)row * Pdim;
    float v = a[tid];
    __shared__ float red[256];
    red[tid] = v;
    __syncthreads();
    for (int s = 128; s > 0; s >>= 1) {
        if (tid < s) red[tid] = fmaxf(red[tid], red[tid + s]);
        __syncthreads();
    }
    float mx = red[0];
    __syncthreads();
    float e = expf(v - mx);
    red[tid] = e;
    __syncthreads();
    for (int s = 128; s > 0; s >>= 1) {
        if (tid < s) red[tid] += red[tid + s];
        __syncthreads();
    }
    a[tid] = e / red[0];
}

// ---------------------------------------------------------------- u = prev + e^{iv} * (attn @ state)
__global__ void k_av() {
    __shared__ float As[16][68];
    __shared__ float Br[16][64], Bi[16][64];
    const int tid = threadIdx.x;
    const int b = blockIdx.z;
    const int p0 = blockIdx.y * 64, n0 = blockIdx.x * 64;
    const int tm = (tid >> 4) * 4, tn = (tid & 15) * 4;
    const int lk = tid & 15, lr = tid >> 4;
    const int ln = tid & 63, lkb = tid >> 6;
    const float* __restrict__ at  = g_attn     + (size_t)b * Pdim * Pdim;
    const float* __restrict__ sre = g_state_re + (size_t)b * Pdim * Ddim;
    const float* __restrict__ sim = g_state_im + (size_t)b * Pdim * Ddim;
    float ar[4][4] = {}, ai[4][4] = {};
    for (int k0 = 0; k0 < Pdim; k0 += 16) {
        #pragma unroll
        for (int i = 0; i < 4; i++)
            As[lk][lr + 16*i] = at[(size_t)(p0 + lr + 16*i) * Pdim + (k0 + lk)];
        #pragma unroll
        for (int i = 0; i < 4; i++) {
            int kq = k0 + lkb * 4 + i;
            Br[lkb*4 + i][ln] = sre[(size_t)kq * Ddim + n0 + ln];
            Bi[lkb*4 + i][ln] = sim[(size_t)kq * Ddim + n0 + ln];
        }
        __syncthreads();
        #pragma unroll
        for (int kk = 0; kk < 16; kk++) {
            float a[4], br[4], bi[4];
            #pragma unroll
            for (int i = 0; i < 4; i++) {
                a[i]  = As[kk][tm+i];
                br[i] = Br[kk][tn+i];
                bi[i] = Bi[kk][tn+i];
            }
            #pragma unroll
            for (int i = 0; i < 4; i++)
                #pragma unroll
                for (int j = 0; j < 4; j++) {
                    ar[i][j] = fmaf(a[i], br[j], ar[i][j]);
                    ai[i][j] = fmaf(a[i], bi[j], ai[i][j]);
                }
        }
        __syncthreads();
    }
    #pragma unroll
    for (int j = 0; j < 4; j++) {
        int d = n0 + tn + j;
        float cv = g_cv[d], sv = g_sv[d];
        #pragma unroll
        for (int i = 0; i < 4; i++) {
            size_t idx = (size_t)b * Pdim * Ddim + (size_t)(p0 + tm + i) * Ddim + d;
            float tr = ar[i][j], ti = ai[i][j];
            g_u_re[idx] = g_state_re[idx] + cv * tr - sv * ti;
            g_u_im[idx] = g_state_im[idx] + sv * tr + cv * ti;
        }
    }
}

// ---------------------------------------------------------------- new = u @ (ffr + i*ffi)
__global__ void k_ff(const float* __restrict__ ffr, const float* __restrict__ ffi) {
    __shared__ float Aur[16][68], Aui[16][68];
    __shared__ float Bfr[16][64], Bfi[16][64];
    const int tid = threadIdx.x;
    const int m0 = blockIdx.y * 64, n0 = blockIdx.x * 64;
    const int tm = (tid >> 4) * 4, tn = (tid & 15) * 4;
    const int lk = tid & 15, lr = tid >> 4;
    const int ln = tid & 63, lkb = tid >> 6;
    float cr[4][4] = {}, ci[4][4] = {};
    for (int k0 = 0; k0 < Ddim; k0 += 16) {
        #pragma unroll
        for (int i = 0; i < 4; i++) {
            size_t ga = (size_t)(m0 + lr + 16*i) * Ddim + (k0 + lk);
            Aur[lk][lr + 16*i] = g_u_re[ga];
            Aui[lk][lr + 16*i] = g_u_im[ga];
        }
        #pragma unroll
        for (int i = 0; i < 4; i++) {
            int kd = k0 + lkb * 4 + i;
            Bfr[lkb*4 + i][ln] = ffr[(size_t)kd * Ddim + n0 + ln];
            Bfi[lkb*4 + i][ln] = ffi[(size_t)kd * Ddim + n0 + ln];
        }
        __syncthreads();
        #pragma unroll
        for (int kk = 0; kk < 16; kk++) {
            float ur[4], ui[4], fr[4], fi[4];
            #pragma unroll
            for (int i = 0; i < 4; i++) {
                ur[i] = Aur[kk][tm+i]; ui[i] = Aui[kk][tm+i];
                fr[i] = Bfr[kk][tn+i]; fi[i] = Bfi[kk][tn+i];
            }
            #pragma unroll
            for (int i = 0; i < 4; i++)
                #pragma unroll
                for (int j = 0; j < 4; j++) {
                    cr[i][j] = fmaf(ur[i],  fr[j], cr[i][j]);
                    cr[i][j] = fmaf(-ui[i], fi[j], cr[i][j]);
                    ci[i][j] = fmaf(ur[i],  fi[j], ci[i][j]);
                    ci[i][j] = fmaf(ui[i],  fr[j], ci[i][j]);
                }
        }
        __syncthreads();
    }
    #pragma unroll
    for (int i = 0; i < 4; i++)
        #pragma unroll
        for (int j = 0; j < 4; j++) {
            size_t idx = (size_t)(m0 + tm + i) * Ddim + (n0 + tn + j);
            g_new_re[idx] = cr[i][j];
            g_new_im[idx] = ci[i][j];
        }
}

// ---------------------------------------------------------------- complex_norm over rows of length D
__global__ void k_norm() {
    const int row = blockIdx.x;
    const int tid = threadIdx.x;
    const size_t base = (size_t)row * Ddim;
    float r0 = g_new_re[base + tid],       i0 = g_new_im[base + tid];
    float r1 = g_new_re[base + tid + 256], i1 = g_new_im[base + tid + 256];
    float m0 = sqrtf(r0*r0 + i0*i0);
    float m1 = sqrtf(r1*r1 + i1*i1);
    __shared__ float s_sum[256], s_sq[256];
    s_sum[tid] = m0 + m1;
    s_sq[tid]  = m0*m0 + m1*m1;
    __syncthreads();
    for (int s = 128; s > 0; s >>= 1) {
        if (tid < s) { s_sum[tid] += s_sum[tid+s]; s_sq[tid] += s_sq[tid+s]; }
        __syncthreads();
    }
    float mean = s_sum[0] * (1.0f / 512.0f);
    float var  = (s_sq[0] - 512.0f * mean * mean) * (1.0f / 511.0f);
    var = fmaxf(var, 0.0f);
    float inv = 1.0f / (sqrtf(var) + 1e-5f);
    float sc0 = tanhf((m0 - mean) * inv) / (m0 + 1e-5f);
    float sc1 = tanhf((m1 - mean) * inv) / (m1 + 1e-5f);
    g_new_re[base + tid]       = r0 * sc0;
    g_new_im[base + tid]       = i0 * sc0;
    g_new_re[base + tid + 256] = r1 * sc1;
    g_new_im[base + tid + 256] = i1 * sc1;
}

// ---------------------------------------------------------------- diff partials (deterministic)
__global__ void k_diff() {
    const int tid = threadIdx.x;
    const size_t start = (size_t)blockIdx.x * 256 + tid;
    double ld = 0.0, lnn = 0.0;
    #pragma unroll
    for (int i = 0; i < 16; i++) {
        size_t idx = start + (size_t)i * (NPART * 256);
        float nr = g_new_re[idx], ni = g_new_im[idx];
        float dr = nr - g_state_re[idx], di = ni - g_state_im[idx];
        ld  += (double)dr * dr + (double)di * di;
        lnn += (double)nr * nr + (double)ni * ni;
    }
    __shared__ double sd[256], sn[256];
    sd[tid] = ld; sn[tid] = lnn;
    __syncthreads();
    for (int s = 128; s > 0; s >>= 1) {
        if (tid < s) { sd[tid] += sd[tid+s]; sn[tid] += sn[tid+s]; }
        __syncthreads();
    }
    if (tid == 0) { g_part_d[blockIdx.x] = sd[0]; g_part_n[blockIdx.x] = sn[0]; }
}

__global__ void k_flag() {
    const int tid = threadIdx.x;
    double ld = 0.0, lnn = 0.0;
    for (int i = tid; i < NPART; i += 256) { ld += g_part_d[i]; lnn += g_part_n[i]; }
    __shared__ double sd[256], sn[256];
    sd[tid] = ld; sn[tid] = lnn;
    __syncthreads();
    for (int s = 128; s > 0; s >>= 1) {
        if (tid < s) { sd[tid] += sd[tid+s]; sn[tid] += sn[tid+s]; }
        __syncthreads();
    }
    if (tid == 0) {
        float diff = (float)(sqrt(sd[0]) / (sqrt(sn[0]) + 1e-8));
        g_commit = g_active;                 // commit uses pre-update active
        if (diff < 1e-3f) g_active = 0;
    }
}

__global__ void k_commit() {
    if (!g_commit) return;
    const size_t start = (size_t)blockIdx.x * 256 + threadIdx.x;
    #pragma unroll
    for (int i = 0; i < 16; i++) {
        size_t idx = start + (size_t)i * (NPART * 256);
        g_state_re[idx] = g_new_re[idx];
        g_state_im[idx] = g_new_im[idx];
    }
}

// ---------------------------------------------------------------- mean pool over P
__global__ void k_pool() {
    const int idx = blockIdx.x * 256 + threadIdx.x;   // b*D + d
    const int b = idx >> 9, d = idx & (Ddim - 1);
    const size_t base = (size_t)b * Pdim * Ddim + d;
    float accr = 0.0f, acci = 0.0f;
    for (int p = 0; p < Pdim; p++) {
        accr += g_state_re[base + (size_t)p * Ddim];
        acci += g_state_im[base + (size_t)p * Ddim];
    }
    g_pool_re[idx] = accr * (1.0f / 256.0f);
    g_pool_im[idx] = acci * (1.0f / 256.0f);
}

// ---------------------------------------------------------------- logits
__global__ void k_logits(float* __restrict__ out, const float* __restrict__ Wr,
                         const float* __restrict__ br, const float* __restrict__ Wi,
                         const float* __restrict__ bi) {
    const int b = blockIdx.x, tid = threadIdx.x;
    float pr0 = g_pool_re[b * Ddim + tid],       pi0 = g_pool_im[b * Ddim + tid];
    float pr1 = g_pool_re[b * Ddim + tid + 256], pi1 = g_pool_im[b * Ddim + tid + 256];
    __shared__ float red[256];
    for (int c = 0; c < Cdim; c++) {
        float v = pr0 * Wr[c * Ddim + tid] + pr1 * Wr[c * Ddim + tid + 256]
                + pi0 * Wi[c * Ddim + tid] + pi1 * Wi[c * Ddim + tid + 256];
        red[tid] = v;
        __syncthreads();
        for (int s = 128; s > 0; s >>= 1) {
            if (tid < s) red[tid] += red[tid+s];
            __syncthreads();
        }
        if (tid == 0) out[b * Cdim + c] = red[0] + br[c] + bi[c];
        __syncthreads();
    }
}

// ---------------------------------------------------------------- launch
extern "C" void kernel_launch(void* const* d_in, const int* in_sizes, int n_in,
                              void* d_out, int out_size) {
    const float* x   = (const float*)d_in[0];
    const float* Wp  = (const float*)d_in[1];
    const float* bp  = (const float*)d_in[2];
    const float* qr  = (const float*)d_in[3];
    const float* kr  = (const float*)d_in[4];
    const float* vr  = (const float*)d_in[5];
    const float* ffr = (const float*)d_in[6];
    const float* ffi = (const float*)d_in[7];
    const float* Wr  = (const float*)d_in[8];
    const float* br  = (const float*)d_in[9];
    const float* Wi  = (const float*)d_in[10];
    const float* bi  = (const float*)d_in[11];
    float* out = (float*)d_out;

    k_prep<<<1, 512>>>(qr, kr, vr);
    k_proj<<<dim3(Ddim/64, (Bdim*Pdim)/64), 256>>>(x, Wp, bp);
    for (int step = 0; step < 4; step++) {
        k_qk<<<dim3(Pdim/64, Pdim/64, Bdim), 256>>>();
        k_softmax<<<Bdim*Pdim, 256>>>();
        k_av<<<dim3(Ddim/64, Pdim/64, Bdim), 256>>>();
        k_ff<<<dim3(Ddim/64, (Bdim*Pdim)/64), 256>>>(ffr, ffi);
        k_norm<<<Bdim*Pdim, 256>>>();
        k_diff<<<NPART, 256>>>();
        k_flag<<<1, 256>>>();
        k_commit<<<NPART, 256>>>();
    }
    k_pool<<<(Bdim*Ddim)/256, 256>>>();
    k_logits<<<Bdim, 256>>>(out, Wr, br, Wi, bi);
}